// round 2
// baseline (speedup 1.0000x reference)
#include <cuda_runtime.h>
#include <math.h>

#define NATOMS 500000
#define NBATCH 1024

typedef unsigned long long u64;

// ---- packed f32x2 helpers (sm_103a FFMA2 path, PTX-only) ----
__device__ __forceinline__ u64 pack2(float x) {
    u64 r; asm("mov.b64 %0, {%1, %1};" : "=l"(r) : "f"(x)); return r;
}
__device__ __forceinline__ void fma2(u64& d, u64 a, u64 b) {
    asm("fma.rn.f32x2 %0, %1, %2, %0;" : "+l"(d) : "l"(a), "l"(b));
}
__device__ __forceinline__ void unpack2(u64 v, float& lo, float& hi) {
    asm("mov.b64 {%0, %1}, %2;" : "=f"(lo), "=f"(hi) : "l"(v));
}

// ---- scratch (device globals: no runtime allocation allowed) ----
__device__ float g_h1[(size_t)NATOMS*64];
__device__ float g_h2[(size_t)NATOMS*64];
__device__ float g_p [(size_t)NATOMS*128];
__device__ int   g_cnt[NBATCH];
__device__ int   g_off[NBATCH+1];
__device__ int   g_cur[NBATCH];
__device__ int   g_sorted[NATOMS];

struct Ptrs { const int* adj[7]; };

__device__ __forceinline__ void seg_of_tile(int bt, int& d, int& t0) {
    // tile counts per degree (64 atoms/tile): 313,1250,2344,2344,1172,313,79
    constexpr int cum[7] = {0,313,1563,3907,6251,7423,7736};
    int dd = 0;
    #pragma unroll
    for (int i = 1; i < 7; i++) if (bt >= cum[i]) dd = i;
    d = dd; t0 = bt - cum[dd];
}
__device__ __forceinline__ int seg_of_atom(int g) {
    constexpr int offs[7] = {0,20000,100000,250000,400000,475000,495000};
    int d = 0;
    #pragma unroll
    for (int i = 1; i < 7; i++) if (g >= offs[i]) d = i;
    return d;
}

// ============================================================
// Unified fused graph-conv (all 7 degree segments in one launch):
// gather(self + neighbor-sum) -> dual GEMM (FFMA2) -> bias ->
// tanh -> batchnorm.  Tile 64 atoms x 64 cols, 256 threads,
// micro-tile 2 atoms x 8 cols (4 f32x2 col-pairs).
// ============================================================
template<int FIN>
__global__ __launch_bounds__(256) void gc_all(
    const float* __restrict__ feat, Ptrs P,
    const float* __restrict__ WnB,   // (MAXDEG, FIN, 64)
    const float* __restrict__ WsB,   // (MAXDEG+1, FIN, 64)
    const float* __restrict__ bB,    // (MAXDEG+1, 64)
    const float* __restrict__ bng, const float* __restrict__ bnb,
    const float* __restrict__ bnm, const float* __restrict__ bnv,
    float* __restrict__ out)
{
    constexpr int XSTR = FIN + 1;
    extern __shared__ float sm[];
    float* s_ws = sm;                          // FIN*64
    float* s_wn = s_ws + FIN*64;               // FIN*64
    float* s_xs = s_wn + FIN*64;               // 64*XSTR
    float* s_xn = s_xs + 64*XSTR;              // 64*XSTR
    float* s_sc = s_xn + 64*XSTR;              // 64
    float* s_sh = s_sc + 64;                   // 64
    float* s_b  = s_sh + 64;                   // 64

    int d, t0; seg_of_tile(blockIdx.x, d, t0);
    constexpr int counts[7] = {20000,80000,150000,150000,75000,20000,5000};
    constexpr int offs[7]   = {0,20000,100000,250000,400000,475000,495000};
    const int cnt = counts[d], gbase = offs[d];
    const float* Ws   = WsB + (size_t)d*FIN*64;
    const float* Wn   = d ? WnB + (size_t)(d-1)*FIN*64 : WsB;  // d0: dummy (xn==0)
    const float* bias = bB + d*64;
    const int*   adj  = P.adj[d];

    const int tid = threadIdx.x;
    for (int i = tid; i < FIN*64; i += 256) { s_ws[i] = Ws[i]; s_wn[i] = Wn[i]; }
    if (tid < 64) {
        float s = bng[tid] * rsqrtf(bnv[tid] + 1e-3f);
        s_sc[tid] = s;
        s_sh[tid] = bnb[tid] - bnm[tid]*s;
        s_b[tid]  = bias[tid];
    }

    const int tile0 = t0 * 64;
    const int wid = tid >> 5, lane = tid & 31;
    constexpr int NR = (FIN + 31) / 32;

    // ---- gather: one warp per atom (stride 8) ----
    for (int a = wid; a < 64; a += 8) {
        int la = tile0 + a;
        float fs[NR], fn[NR];
        #pragma unroll
        for (int r = 0; r < NR; r++) { fs[r] = 0.f; fn[r] = 0.f; }
        if (la < cnt) {
            const float* row = feat + (size_t)(gbase + la) * FIN;
            #pragma unroll
            for (int r = 0; r < NR; r++) {
                int k = lane + 32*r;
                if ((FIN % 32 == 0) || k < FIN) fs[r] = row[k];
            }
            for (int j = 0; j < d; j++) {
                int nb = adj[(size_t)la * d + j];
                const float* nr = feat + (size_t)nb * FIN;
                #pragma unroll
                for (int r = 0; r < NR; r++) {
                    int k = lane + 32*r;
                    if ((FIN % 32 == 0) || k < FIN) fn[r] += nr[k];
                }
            }
        }
        #pragma unroll
        for (int r = 0; r < NR; r++) {
            int k = lane + 32*r;
            if ((FIN % 32 == 0) || k < FIN) {
                s_xs[a*XSTR + k] = fs[r];
                s_xn[a*XSTR + k] = fn[r];
            }
        }
    }
    __syncthreads();

    // ---- GEMM: 2 atoms x 8 cols per thread, FFMA2 ----
    const int ta = tid >> 3;    // 0..31 -> atoms 2ta, 2ta+1
    const int tx = tid & 7;     // 0..7  -> cols tx*8..tx*8+7
    u64 acc[2][4] = {{0,0,0,0},{0,0,0,0}};

    const float* xs0 = &s_xs[(2*ta  ) * XSTR];
    const float* xs1 = &s_xs[(2*ta+1) * XSTR];
    const float* xn0 = &s_xn[(2*ta  ) * XSTR];
    const float* xn1 = &s_xn[(2*ta+1) * XSTR];
    const float* wsp = &s_ws[tx*8];
    const float* wnp = &s_wn[tx*8];

    #pragma unroll 4
    for (int k = 0; k < FIN; k++) {
        ulonglong2 wsA = *reinterpret_cast<const ulonglong2*>(wsp + k*64);
        ulonglong2 wsB = *reinterpret_cast<const ulonglong2*>(wsp + k*64 + 4);
        ulonglong2 wnA = *reinterpret_cast<const ulonglong2*>(wnp + k*64);
        ulonglong2 wnB = *reinterpret_cast<const ulonglong2*>(wnp + k*64 + 4);
        u64 a0 = pack2(xs0[k]), a1 = pack2(xs1[k]);
        u64 b0 = pack2(xn0[k]), b1 = pack2(xn1[k]);
        fma2(acc[0][0], a0, wsA.x); fma2(acc[0][1], a0, wsA.y);
        fma2(acc[0][2], a0, wsB.x); fma2(acc[0][3], a0, wsB.y);
        fma2(acc[0][0], b0, wnA.x); fma2(acc[0][1], b0, wnA.y);
        fma2(acc[0][2], b0, wnB.x); fma2(acc[0][3], b0, wnB.y);
        fma2(acc[1][0], a1, wsA.x); fma2(acc[1][1], a1, wsA.y);
        fma2(acc[1][2], a1, wsB.x); fma2(acc[1][3], a1, wsB.y);
        fma2(acc[1][0], b1, wnA.x); fma2(acc[1][1], b1, wnA.y);
        fma2(acc[1][2], b1, wnB.x); fma2(acc[1][3], b1, wnB.y);
    }

    // ---- epilogue: bias -> tanh -> bn -> store ----
    const int c0 = tx * 8;
    #pragma unroll
    for (int i = 0; i < 2; i++) {
        int la = tile0 + 2*ta + i;
        if (la < cnt) {
            float o[8];
            #pragma unroll
            for (int p = 0; p < 4; p++) {
                float lo, hi; unpack2(acc[i][p], lo, hi);
                int c = c0 + 2*p;
                o[2*p]   = tanhf(lo + s_b[c  ]) * s_sc[c  ] + s_sh[c  ];
                o[2*p+1] = tanhf(hi + s_b[c+1]) * s_sc[c+1] + s_sh[c+1];
            }
            float4* dst = reinterpret_cast<float4*>(&out[(size_t)(gbase + la)*64 + c0]);
            dst[0] = make_float4(o[0],o[1],o[2],o[3]);
            dst[1] = make_float4(o[4],o[5],o[6],o[7]);
        }
    }
}

// ============================================================
// Unified graph_pool (single launch, all segments).
// One warp per atom, float2 per lane.
// ============================================================
__global__ __launch_bounds__(256) void pool_all(
    const float* __restrict__ in, Ptrs P, float* __restrict__ out)
{
    int g    = (blockIdx.x * 256 + threadIdx.x) >> 5;
    int lane = threadIdx.x & 31;
    if (g >= NATOMS) return;
    constexpr int offs[7] = {0,20000,100000,250000,400000,475000,495000};
    int d = seg_of_atom(g);
    int la = g - offs[d];
    float2 m = reinterpret_cast<const float2*>(in + (size_t)g*64)[lane];
    const int* adj = P.adj[d];
    for (int j = 0; j < d; j++) {
        int nb = adj[(size_t)la * d + j];
        float2 v = reinterpret_cast<const float2*>(in + (size_t)nb*64)[lane];
        m.x = fmaxf(m.x, v.x);
        m.y = fmaxf(m.y, v.y);
    }
    reinterpret_cast<float2*>(out + (size_t)g*64)[lane] = m;
}

// ============================================================
// d1: dense (N x 64) @ (64 x 128) + bias -> tanh -> bn3 -> p
// Tile 64 atoms x 128 cols, 256 threads, 4 atoms x 8 cols, FFMA2.
// ============================================================
__global__ __launch_bounds__(256) void d1_kernel(
    const float* __restrict__ in, const float* __restrict__ W,
    const float* __restrict__ b,
    const float* __restrict__ bng, const float* __restrict__ bnb,
    const float* __restrict__ bnm, const float* __restrict__ bnv,
    float* __restrict__ out)
{
    extern __shared__ float sm[];
    float* s_w  = sm;                 // 64*128
    float* s_x  = s_w + 64*128;       // 64*65
    float* s_sc = s_x + 64*65;        // 128
    float* s_sh = s_sc + 128;         // 128
    float* s_b  = s_sh + 128;         // 128

    const int tid = threadIdx.x;
    for (int i = tid; i < 64*128; i += 256) s_w[i] = W[i];
    if (tid < 128) {
        float s = bng[tid] * rsqrtf(bnv[tid] + 1e-3f);
        s_sc[tid] = s;
        s_sh[tid] = bnb[tid] - bnm[tid]*s;
        s_b[tid]  = b[tid];
    }
    const int tile0 = blockIdx.x * 64;
    for (int i = tid; i < 64*64; i += 256) {
        int a = i >> 6, k = i & 63;
        int la = tile0 + a;
        s_x[a*65 + k] = (la < NATOMS) ? in[(size_t)la*64 + k] : 0.f;
    }
    __syncthreads();

    const int tx = tid & 15;   // cols tx*8..+7 (128 cols)
    const int ty = tid >> 4;   // atoms ty*4..+3
    u64 acc[4][4] = {{0,0,0,0},{0,0,0,0},{0,0,0,0},{0,0,0,0}};
    const float* wp = &s_w[tx*8];
    const float* xp = &s_x[(ty*4)*65];

    #pragma unroll 4
    for (int k = 0; k < 64; k++) {
        ulonglong2 wA = *reinterpret_cast<const ulonglong2*>(wp + k*128);
        ulonglong2 wB = *reinterpret_cast<const ulonglong2*>(wp + k*128 + 4);
        #pragma unroll
        for (int i = 0; i < 4; i++) {
            u64 x2 = pack2(xp[i*65 + k]);
            fma2(acc[i][0], x2, wA.x); fma2(acc[i][1], x2, wA.y);
            fma2(acc[i][2], x2, wB.x); fma2(acc[i][3], x2, wB.y);
        }
    }
    const int c0 = tx * 8;
    #pragma unroll
    for (int i = 0; i < 4; i++) {
        int la = tile0 + ty*4 + i;
        if (la < NATOMS) {
            float o[8];
            #pragma unroll
            for (int p = 0; p < 4; p++) {
                float lo, hi; unpack2(acc[i][p], lo, hi);
                int c = c0 + 2*p;
                o[2*p]   = tanhf(lo + s_b[c  ]) * s_sc[c  ] + s_sh[c  ];
                o[2*p+1] = tanhf(hi + s_b[c+1]) * s_sc[c+1] + s_sh[c+1];
            }
            float4* dst = reinterpret_cast<float4*>(&out[(size_t)la*128 + c0]);
            dst[0] = make_float4(o[0],o[1],o[2],o[3]);
            dst[1] = make_float4(o[4],o[5],o[6],o[7]);
        }
    }
}

// ============================================================
// counting sort of atoms by membership
// ============================================================
__global__ void zero_cnt_kernel() {
    int i = blockIdx.x * blockDim.x + threadIdx.x;
    if (i < NBATCH) g_cnt[i] = 0;
}
__global__ void hist_kernel(const int* __restrict__ mem) {
    int i = blockIdx.x * blockDim.x + threadIdx.x;
    if (i < NATOMS) atomicAdd(&g_cnt[mem[i]], 1);
}
__global__ void scan_kernel() {   // 1 block, 1024 threads
    __shared__ int s[NBATCH];
    int t = threadIdx.x;
    s[t] = g_cnt[t];
    __syncthreads();
    for (int ofs = 1; ofs < NBATCH; ofs <<= 1) {
        int v = (t >= ofs) ? s[t - ofs] : 0;
        __syncthreads();
        s[t] += v;
        __syncthreads();
    }
    g_off[t+1] = s[t];
    if (t == 0) g_off[0] = 0;
    g_cur[t] = s[t] - g_cnt[t];
}
__global__ void scatter_kernel(const int* __restrict__ mem) {
    int i = blockIdx.x * blockDim.x + threadIdx.x;
    if (i < NATOMS) {
        int p = atomicAdd(&g_cur[mem[i]], 1);
        g_sorted[p] = i;
    }
}

// ============================================================
// graph_gather (segment sum + max) -> tanh -> d2+sigmoid -> d3.
// ============================================================
__global__ __launch_bounds__(128) void reduce_kernel(
    const float* __restrict__ d2W, const float* __restrict__ d2b,
    const float* __restrict__ d3W, const float* __restrict__ d3b,
    float* __restrict__ outp)
{
    __shared__ float gs[256];
    __shared__ int   sidx[512];
    __shared__ float ssig[64];
    const int b = blockIdx.x, t = threadIdx.x;
    const int start = g_off[b], end = g_off[b+1];

    float sum = 0.f;
    float mx  = -INFINITY;
    for (int base = start; base < end; base += 512) {
        int n = min(512, end - base);
        for (int i = t; i < n; i += 128) sidx[i] = g_sorted[base + i];
        __syncthreads();
        int i = 0;
        for (; i + 4 <= n; i += 4) {
            float v0 = g_p[(size_t)sidx[i+0]*128 + t];
            float v1 = g_p[(size_t)sidx[i+1]*128 + t];
            float v2 = g_p[(size_t)sidx[i+2]*128 + t];
            float v3 = g_p[(size_t)sidx[i+3]*128 + t];
            sum += (v0 + v1) + (v2 + v3);
            mx = fmaxf(mx, fmaxf(fmaxf(v0, v1), fmaxf(v2, v3)));
        }
        for (; i < n; i++) {
            float v = g_p[(size_t)sidx[i]*128 + t];
            sum += v;
            mx = fmaxf(mx, v);
        }
        __syncthreads();
    }
    gs[t]       = tanhf(sum);
    gs[128 + t] = tanhf(mx);
    __syncthreads();

    if (t < 64) {
        float a = d2b[t];
        #pragma unroll 4
        for (int k = 0; k < 256; k++) a += gs[k] * __ldg(&d2W[k*64 + t]);
        ssig[t] = 1.f / (1.f + expf(-a));
    }
    __syncthreads();
    if (t < 32) {
        float v = ssig[t]*__ldg(&d3W[t]) + ssig[t+32]*__ldg(&d3W[t+32]);
        #pragma unroll
        for (int o = 16; o; o >>= 1) v += __shfl_down_sync(0xffffffffu, v, o);
        if (t == 0) outp[b] = v + d3b[0];
    }
}

// ============================================================
extern "C" void kernel_launch(void* const* d_in, const int* in_sizes, int n_in,
                              void* d_out, int out_size)
{
    const float* feat       = (const float*)d_in[0];
    const int*   membership = (const int*)  d_in[1];
    Ptrs P;
    P.adj[0] = nullptr;
    for (int d = 1; d <= 6; d++) P.adj[d] = (const int*)d_in[1 + d];
    const float* gc1_Wn = (const float*)d_in[8];
    const float* gc1_Ws = (const float*)d_in[9];
    const float* gc1_b  = (const float*)d_in[10];
    const float* gc2_Wn = (const float*)d_in[11];
    const float* gc2_Ws = (const float*)d_in[12];
    const float* gc2_b  = (const float*)d_in[13];
    const float* bn1g = (const float*)d_in[14];
    const float* bn1b = (const float*)d_in[15];
    const float* bn1m = (const float*)d_in[16];
    const float* bn1v = (const float*)d_in[17];
    const float* bn3g = (const float*)d_in[18];
    const float* bn3b = (const float*)d_in[19];
    const float* bn3m = (const float*)d_in[20];
    const float* bn3v = (const float*)d_in[21];
    const float* d1W = (const float*)d_in[22];
    const float* d1b = (const float*)d_in[23];
    const float* d2W = (const float*)d_in[24];
    const float* d2b = (const float*)d_in[25];
    const float* d3W = (const float*)d_in[26];
    const float* d3b = (const float*)d_in[27];

    void* pp;
    cudaGetSymbolAddress(&pp, g_h1); float* h1 = (float*)pp;
    cudaGetSymbolAddress(&pp, g_h2); float* h2 = (float*)pp;
    cudaGetSymbolAddress(&pp, g_p);  float* pf = (float*)pp;

    const int SM75 = (75*64*2 + 64*76*2 + 192) * 4;   // 78080 B
    const int SM64 = (64*64*2 + 64*65*2 + 192) * 4;   // 66816 B
    const int SMD1 = (64*128 + 64*65 + 384) * 4;      // 50944 B
    cudaFuncSetAttribute(gc_all<75>, cudaFuncAttributeMaxDynamicSharedMemorySize, SM75);
    cudaFuncSetAttribute(gc_all<64>, cudaFuncAttributeMaxDynamicSharedMemorySize, SM64);
    cudaFuncSetAttribute(d1_kernel,  cudaFuncAttributeMaxDynamicSharedMemorySize, SMD1);

    const int GC_GRID   = 7815;   // sum of per-degree 64-atom tiles
    const int POOL_GRID = (NATOMS*32 + 255) / 256;

    // gc1 + bn1 -> h1
    gc_all<75><<<GC_GRID, 256, SM75>>>(feat, P, gc1_Wn, gc1_Ws, gc1_b,
                                       bn1g, bn1b, bn1m, bn1v, h1);
    // pool1 -> h2
    pool_all<<<POOL_GRID, 256>>>(h1, P, h2);
    // gc2 + bn1 -> h1
    gc_all<64><<<GC_GRID, 256, SM64>>>(h2, P, gc2_Wn, gc2_Ws, gc2_b,
                                       bn1g, bn1b, bn1m, bn1v, h1);
    // pool2 -> h2
    pool_all<<<POOL_GRID, 256>>>(h1, P, h2);
    // d1 + tanh + bn3 -> p
    d1_kernel<<<(NATOMS + 63)/64, 256, SMD1>>>(h2, d1W, d1b,
                                               bn3g, bn3b, bn3m, bn3v, pf);

    // counting sort by membership
    zero_cnt_kernel<<<(NBATCH + 255)/256, 256>>>();
    hist_kernel<<<(NATOMS + 255)/256, 256>>>(membership);
    scan_kernel<<<1, 1024>>>();
    scatter_kernel<<<(NATOMS + 255)/256, 256>>>(membership);

    // segment reduce + final MLP -> out
    reduce_kernel<<<NBATCH, 128>>>(d2W, d2b, d3W, d3b, (float*)d_out);
}

// round 3
// speedup vs baseline: 1.3887x; 1.3887x over previous
#include <cuda_runtime.h>
#include <math.h>

#define NATOMS 500000
#define NBATCH 1024

// ---- scratch (device globals: no runtime allocation allowed) ----
__device__ float g_h1[(size_t)NATOMS*64];
__device__ float g_h2[(size_t)NATOMS*64];
__device__ float g_p [(size_t)NATOMS*128];
__device__ int   g_cnt[NBATCH];
__device__ int   g_off[NBATCH+1];
__device__ int   g_cur[NBATCH];
__device__ int   g_sorted[NATOMS];

struct Ptrs { const int* adj[7]; };

__device__ __forceinline__ void seg_of_tile(int bt, int& d, int& t0) {
    // 64-atom tiles per degree: 313,1250,2344,2344,1172,313,79 (cum below)
    constexpr int cum[7] = {0,313,1563,3907,6251,7423,7736};
    int dd = 0;
    #pragma unroll
    for (int i = 1; i < 7; i++) if (bt >= cum[i]) dd = i;
    d = dd; t0 = bt - cum[dd];
}
__device__ __forceinline__ int seg_of_atom(int g) {
    constexpr int offs[7] = {0,20000,100000,250000,400000,475000,495000};
    int d = 0;
    #pragma unroll
    for (int i = 1; i < 7; i++) if (g >= offs[i]) d = i;
    return d;
}

// ============================================================
// Unified fused graph-conv: gather(self+nbr-sum as float2) ->
// dual GEMM -> bias -> tanh -> bn.  64-atom x 64-col tile,
// 512 threads, micro-tile 2 atoms x 4 cols, 2 CTAs/SM.
// ============================================================
template<int FIN>
__global__ __launch_bounds__(512, 2) void gc_all(
    const float* __restrict__ feat, Ptrs P,
    const float* __restrict__ WnB,   // (6, FIN, 64)
    const float* __restrict__ WsB,   // (7, FIN, 64)
    const float* __restrict__ bB,    // (7, 64)
    const float* __restrict__ bng, const float* __restrict__ bnb,
    const float* __restrict__ bnm, const float* __restrict__ bnv,
    float* __restrict__ out)
{
    extern __shared__ float sm[];
    float*  s_ws = sm;                          // FIN*64
    float*  s_wn = s_ws + FIN*64;               // FIN*64
    float2* s_x  = reinterpret_cast<float2*>(s_wn + FIN*64); // 64*FIN float2
    float*  s_sc = s_wn + FIN*64 + 64*FIN*2;    // 64
    float*  s_sh = s_sc + 64;                   // 64
    float*  s_b  = s_sh + 64;                   // 64

    int d, t0; seg_of_tile(blockIdx.x, d, t0);
    constexpr int counts[7] = {20000,80000,150000,150000,75000,20000,5000};
    constexpr int offs[7]   = {0,20000,100000,250000,400000,475000,495000};
    const int cnt = counts[d], gbase = offs[d];
    const float* Ws   = WsB + (size_t)d*FIN*64;
    const float* Wn   = d ? WnB + (size_t)(d-1)*FIN*64 : WsB; // d0 dummy (xn==0)
    const float* bias = bB + d*64;
    const int*   adj  = P.adj[d];

    const int tid = threadIdx.x;
    for (int i = tid; i < FIN*64; i += 512) { s_ws[i] = Ws[i]; s_wn[i] = Wn[i]; }
    if (tid < 64) {
        float s = bng[tid] * rsqrtf(bnv[tid] + 1e-3f);
        s_sc[tid] = s;
        s_sh[tid] = bnb[tid] - bnm[tid]*s;
        s_b[tid]  = bias[tid];
    }

    const int tile0 = t0 * 64;
    const int wid = tid >> 5, lane = tid & 31;
    constexpr int NR = (FIN + 31) / 32;

    // ---- gather: warp per atom (16 warps, stride 16) ----
    for (int a = wid; a < 64; a += 16) {
        int la = tile0 + a;
        float fs[NR], fn[NR];
        #pragma unroll
        for (int r = 0; r < NR; r++) { fs[r] = 0.f; fn[r] = 0.f; }
        if (la < cnt) {
            const float* row = feat + (size_t)(gbase + la) * FIN;
            #pragma unroll
            for (int r = 0; r < NR; r++) {
                int k = lane + 32*r;
                if ((FIN % 32 == 0) || k < FIN) fs[r] = row[k];
            }
            for (int j = 0; j < d; j++) {
                int nb = adj[(size_t)la * d + j];
                const float* nr = feat + (size_t)nb * FIN;
                #pragma unroll
                for (int r = 0; r < NR; r++) {
                    int k = lane + 32*r;
                    if ((FIN % 32 == 0) || k < FIN) fn[r] += nr[k];
                }
            }
        }
        #pragma unroll
        for (int r = 0; r < NR; r++) {
            int k = lane + 32*r;
            if ((FIN % 32 == 0) || k < FIN)
                s_x[a*FIN + k] = make_float2(fs[r], fn[r]);
        }
    }
    __syncthreads();

    // ---- GEMM: 2 atoms x 4 cols per thread ----
    const int ty = tid >> 4;    // 0..31 -> atoms 2ty, 2ty+1
    const int tx = tid & 15;    // 0..15 -> cols tx*4..+3
    float acc0[4] = {0,0,0,0};
    float acc1[4] = {0,0,0,0};
    const float2* x0 = &s_x[(2*ty  ) * FIN];
    const float2* x1 = &s_x[(2*ty+1) * FIN];
    const float*  wsp = &s_ws[tx*4];
    const float*  wnp = &s_wn[tx*4];

    #pragma unroll 5
    for (int k = 0; k < FIN; k++) {
        float4 w4  = *reinterpret_cast<const float4*>(wsp + k*64);
        float4 wn4 = *reinterpret_cast<const float4*>(wnp + k*64);
        float2 a0 = x0[k];
        float2 a1 = x1[k];
        acc0[0] += a0.x*w4.x + a0.y*wn4.x;
        acc0[1] += a0.x*w4.y + a0.y*wn4.y;
        acc0[2] += a0.x*w4.z + a0.y*wn4.z;
        acc0[3] += a0.x*w4.w + a0.y*wn4.w;
        acc1[0] += a1.x*w4.x + a1.y*wn4.x;
        acc1[1] += a1.x*w4.y + a1.y*wn4.y;
        acc1[2] += a1.x*w4.z + a1.y*wn4.z;
        acc1[3] += a1.x*w4.w + a1.y*wn4.w;
    }

    // ---- epilogue: bias -> tanh -> bn -> store ----
    const int c0 = tx << 2;
    #pragma unroll
    for (int i = 0; i < 2; i++) {
        int la = tile0 + 2*ty + i;
        if (la < cnt) {
            const float* ac = i ? acc1 : acc0;
            float4 o;
            o.x = tanhf(ac[0] + s_b[c0+0]) * s_sc[c0+0] + s_sh[c0+0];
            o.y = tanhf(ac[1] + s_b[c0+1]) * s_sc[c0+1] + s_sh[c0+1];
            o.z = tanhf(ac[2] + s_b[c0+2]) * s_sc[c0+2] + s_sh[c0+2];
            o.w = tanhf(ac[3] + s_b[c0+3]) * s_sc[c0+3] + s_sh[c0+3];
            *reinterpret_cast<float4*>(&out[(size_t)(gbase + la)*64 + c0]) = o;
        }
    }
}

// ============================================================
// graph_pool: half-warp (16 lanes) per atom, float4 per lane.
// ============================================================
__global__ __launch_bounds__(256) void pool_all(
    const float* __restrict__ in, Ptrs P, float* __restrict__ out)
{
    int g = (blockIdx.x * 256 + threadIdx.x) >> 4;
    int l = threadIdx.x & 15;
    if (g >= NATOMS) return;
    constexpr int offs[7] = {0,20000,100000,250000,400000,475000,495000};
    int d = seg_of_atom(g);
    int la = g - offs[d];
    float4 m = reinterpret_cast<const float4*>(in + (size_t)g*64)[l];
    const int* adj = P.adj[d];
    for (int j = 0; j < d; j++) {
        int nb = adj[(size_t)la * d + j];
        float4 v = reinterpret_cast<const float4*>(in + (size_t)nb*64)[l];
        m.x = fmaxf(m.x, v.x);
        m.y = fmaxf(m.y, v.y);
        m.z = fmaxf(m.z, v.z);
        m.w = fmaxf(m.w, v.w);
    }
    reinterpret_cast<float4*>(out + (size_t)g*64)[l] = m;
}

// ============================================================
// d1: dense (N x 64) @ (64 x 128) + bias -> tanh -> bn3 -> p
// Tile 64 atoms x 128 cols, 256 threads, 8 atoms x 4 cols.
// ============================================================
__global__ __launch_bounds__(256) void d1_kernel(
    const float* __restrict__ in, const float* __restrict__ W,
    const float* __restrict__ b,
    const float* __restrict__ bng, const float* __restrict__ bnb,
    const float* __restrict__ bnm, const float* __restrict__ bnv,
    float* __restrict__ out)
{
    extern __shared__ float sm[];
    float* s_w  = sm;                 // 64*128
    float* s_x  = s_w + 64*128;       // 64*65
    float* s_sc = s_x + 64*65;        // 128
    float* s_sh = s_sc + 128;         // 128
    float* s_b  = s_sh + 128;         // 128

    const int tid = threadIdx.x;
    for (int i = tid; i < 64*128; i += 256) s_w[i] = W[i];
    if (tid < 128) {
        float s = bng[tid] * rsqrtf(bnv[tid] + 1e-3f);
        s_sc[tid] = s;
        s_sh[tid] = bnb[tid] - bnm[tid]*s;
        s_b[tid]  = b[tid];
    }
    const int tile0 = blockIdx.x * 64;
    for (int i = tid; i < 64*64; i += 256) {
        int a = i >> 6, k = i & 63;
        int la = tile0 + a;
        s_x[a*65 + k] = (la < NATOMS) ? in[(size_t)la*64 + k] : 0.f;
    }
    __syncthreads();

    const int tx = tid & 31;   // 32 col-quads -> 128 cols
    const int ty = tid >> 5;   // 8 groups -> 8 atoms each
    float acc[8][4] = {};
    #pragma unroll 4
    for (int k = 0; k < 64; k++) {
        float4 w4 = *reinterpret_cast<const float4*>(&s_w[k*128 + (tx<<2)]);
        #pragma unroll
        for (int i = 0; i < 8; i++) {
            float x = s_x[(ty*8+i)*65 + k];
            acc[i][0] += x*w4.x;
            acc[i][1] += x*w4.y;
            acc[i][2] += x*w4.z;
            acc[i][3] += x*w4.w;
        }
    }
    const int c0 = tx << 2;
    #pragma unroll
    for (int i = 0; i < 8; i++) {
        int la = tile0 + ty*8 + i;
        if (la < NATOMS) {
            float4 o;
            o.x = tanhf(acc[i][0] + s_b[c0+0]) * s_sc[c0+0] + s_sh[c0+0];
            o.y = tanhf(acc[i][1] + s_b[c0+1]) * s_sc[c0+1] + s_sh[c0+1];
            o.z = tanhf(acc[i][2] + s_b[c0+2]) * s_sc[c0+2] + s_sh[c0+2];
            o.w = tanhf(acc[i][3] + s_b[c0+3]) * s_sc[c0+3] + s_sh[c0+3];
            *reinterpret_cast<float4*>(&out[(size_t)la*128 + c0]) = o;
        }
    }
}

// ============================================================
// counting sort of atoms by membership
// ============================================================
__global__ void zero_cnt_kernel() {
    int i = blockIdx.x * blockDim.x + threadIdx.x;
    if (i < NBATCH) g_cnt[i] = 0;
}
__global__ void hist_kernel(const int* __restrict__ mem) {
    int i = blockIdx.x * blockDim.x + threadIdx.x;
    if (i < NATOMS) atomicAdd(&g_cnt[mem[i]], 1);
}
__global__ void scan_kernel() {   // 1 block, 1024 threads
    __shared__ int s[NBATCH];
    int t = threadIdx.x;
    s[t] = g_cnt[t];
    __syncthreads();
    for (int ofs = 1; ofs < NBATCH; ofs <<= 1) {
        int v = (t >= ofs) ? s[t - ofs] : 0;
        __syncthreads();
        s[t] += v;
        __syncthreads();
    }
    g_off[t+1] = s[t];
    if (t == 0) g_off[0] = 0;
    g_cur[t] = s[t] - g_cnt[t];
}
__global__ void scatter_kernel(const int* __restrict__ mem) {
    int i = blockIdx.x * blockDim.x + threadIdx.x;
    if (i < NATOMS) {
        int p = atomicAdd(&g_cur[mem[i]], 1);
        g_sorted[p] = i;
    }
}

// ============================================================
// graph_gather (segment sum + max) -> tanh -> d2+sigmoid -> d3.
// ============================================================
__global__ __launch_bounds__(128) void reduce_kernel(
    const float* __restrict__ d2W, const float* __restrict__ d2b,
    const float* __restrict__ d3W, const float* __restrict__ d3b,
    float* __restrict__ outp)
{
    __shared__ float gs[256];
    __shared__ int   sidx[512];
    __shared__ float ssig[64];
    const int b = blockIdx.x, t = threadIdx.x;
    const int start = g_off[b], end = g_off[b+1];

    float sum = 0.f;
    float mx  = -INFINITY;
    for (int base = start; base < end; base += 512) {
        int n = min(512, end - base);
        for (int i = t; i < n; i += 128) sidx[i] = g_sorted[base + i];
        __syncthreads();
        int i = 0;
        for (; i + 4 <= n; i += 4) {
            float v0 = g_p[(size_t)sidx[i+0]*128 + t];
            float v1 = g_p[(size_t)sidx[i+1]*128 + t];
            float v2 = g_p[(size_t)sidx[i+2]*128 + t];
            float v3 = g_p[(size_t)sidx[i+3]*128 + t];
            sum += (v0 + v1) + (v2 + v3);
            mx = fmaxf(mx, fmaxf(fmaxf(v0, v1), fmaxf(v2, v3)));
        }
        for (; i < n; i++) {
            float v = g_p[(size_t)sidx[i]*128 + t];
            sum += v;
            mx = fmaxf(mx, v);
        }
        __syncthreads();
    }
    gs[t]       = tanhf(sum);
    gs[128 + t] = tanhf(mx);
    __syncthreads();

    if (t < 64) {
        float a = d2b[t];
        #pragma unroll 4
        for (int k = 0; k < 256; k++) a += gs[k] * __ldg(&d2W[k*64 + t]);
        ssig[t] = 1.f / (1.f + expf(-a));
    }
    __syncthreads();
    if (t < 32) {
        float v = ssig[t]*__ldg(&d3W[t]) + ssig[t+32]*__ldg(&d3W[t+32]);
        #pragma unroll
        for (int o = 16; o; o >>= 1) v += __shfl_down_sync(0xffffffffu, v, o);
        if (t == 0) outp[b] = v + d3b[0];
    }
}

// ============================================================
extern "C" void kernel_launch(void* const* d_in, const int* in_sizes, int n_in,
                              void* d_out, int out_size)
{
    const float* feat       = (const float*)d_in[0];
    const int*   membership = (const int*)  d_in[1];
    Ptrs P;
    P.adj[0] = nullptr;
    for (int d = 1; d <= 6; d++) P.adj[d] = (const int*)d_in[1 + d];
    const float* gc1_Wn = (const float*)d_in[8];
    const float* gc1_Ws = (const float*)d_in[9];
    const float* gc1_b  = (const float*)d_in[10];
    const float* gc2_Wn = (const float*)d_in[11];
    const float* gc2_Ws = (const float*)d_in[12];
    const float* gc2_b  = (const float*)d_in[13];
    const float* bn1g = (const float*)d_in[14];
    const float* bn1b = (const float*)d_in[15];
    const float* bn1m = (const float*)d_in[16];
    const float* bn1v = (const float*)d_in[17];
    const float* bn3g = (const float*)d_in[18];
    const float* bn3b = (const float*)d_in[19];
    const float* bn3m = (const float*)d_in[20];
    const float* bn3v = (const float*)d_in[21];
    const float* d1W = (const float*)d_in[22];
    const float* d1b = (const float*)d_in[23];
    const float* d2W = (const float*)d_in[24];
    const float* d2b = (const float*)d_in[25];
    const float* d3W = (const float*)d_in[26];
    const float* d3b = (const float*)d_in[27];

    void* pp;
    cudaGetSymbolAddress(&pp, g_h1); float* h1 = (float*)pp;
    cudaGetSymbolAddress(&pp, g_h2); float* h2 = (float*)pp;
    cudaGetSymbolAddress(&pp, g_p);  float* pf = (float*)pp;

    const int SM75 = (75*64*2 + 64*75*2 + 192) * 4;   // 77,568 B
    const int SM64 = (64*64*2 + 64*64*2 + 192) * 4;   // 66,304 B
    const int SMD1 = (64*128 + 64*65 + 384) * 4;      // 50,944 B
    cudaFuncSetAttribute(gc_all<75>, cudaFuncAttributeMaxDynamicSharedMemorySize, SM75);
    cudaFuncSetAttribute(gc_all<64>, cudaFuncAttributeMaxDynamicSharedMemorySize, SM64);
    cudaFuncSetAttribute(d1_kernel,  cudaFuncAttributeMaxDynamicSharedMemorySize, SMD1);

    const int GC_GRID   = 7815;                    // sum of 64-atom tiles
    const int POOL_GRID = (NATOMS*16 + 255) / 256; // half-warp per atom

    // gc1 + bn1 -> h1
    gc_all<75><<<GC_GRID, 512, SM75>>>(feat, P, gc1_Wn, gc1_Ws, gc1_b,
                                       bn1g, bn1b, bn1m, bn1v, h1);
    // pool1 -> h2
    pool_all<<<POOL_GRID, 256>>>(h1, P, h2);
    // gc2 + bn1 -> h1
    gc_all<64><<<GC_GRID, 512, SM64>>>(h2, P, gc2_Wn, gc2_Ws, gc2_b,
                                       bn1g, bn1b, bn1m, bn1v, h1);
    // pool2 -> h2
    pool_all<<<POOL_GRID, 256>>>(h1, P, h2);
    // d1 + tanh + bn3 -> p
    d1_kernel<<<(NATOMS + 63)/64, 256, SMD1>>>(h2, d1W, d1b,
                                               bn3g, bn3b, bn3m, bn3v, pf);

    // counting sort by membership
    zero_cnt_kernel<<<(NBATCH + 255)/256, 256>>>();
    hist_kernel<<<(NATOMS + 255)/256, 256>>>(membership);
    scan_kernel<<<1, 1024>>>();
    scatter_kernel<<<(NATOMS + 255)/256, 256>>>(membership);

    // segment reduce + final MLP -> out
    reduce_kernel<<<NBATCH, 128>>>(d2W, d2b, d3W, d3b, (float*)d_out);
}

// round 5
// speedup vs baseline: 1.7911x; 1.2898x over previous
#include <cuda_runtime.h>
#include <cuda_bf16.h>
#include <math.h>
#include <cstdint>

#define NATOMS 500000
#define NBATCH 1024

// ================= scratch =================
__device__ float g_h1[(size_t)NATOMS*64];
__device__ float g_h2[(size_t)NATOMS*64];
__device__ float g_p [(size_t)NATOMS*128];
__device__ int   g_cnt[NBATCH];
__device__ int   g_off[NBATCH+1];
__device__ int   g_cur[NBATCH];
__device__ int   g_sorted[NATOMS];
// pre-transposed, bf16-split, pre-swizzled weight images ([n][KPAD] phys layout)
__device__ __align__(16) __nv_bfloat16 g_B1h[7*64*192];
__device__ __align__(16) __nv_bfloat16 g_B1l[7*64*192];
__device__ __align__(16) __nv_bfloat16 g_B2h[7*64*128];
__device__ __align__(16) __nv_bfloat16 g_B2l[7*64*128];
__device__ __align__(16) __nv_bfloat16 g_Bdh[128*64];
__device__ __align__(16) __nv_bfloat16 g_Bdl[128*64];

struct Ptrs { const int* adj[7]; };

// ================= helpers =================
__device__ __forceinline__ uint32_t smem_u32(const void* p) {
    uint32_t a;
    asm("{ .reg .u64 t; cvta.to.shared.u64 t, %1; cvt.u32.u64 %0, t; }" : "=r"(a) : "l"(p));
    return a;
}
// physical byte offset in a [row][k] bf16 image with 16B-chunk swizzle:
// chunk = (k>>3) ^ (row&7)  (conflict-free ldmatrix; rows stride multiple of 128B)
__device__ __forceinline__ uint32_t phys(int row, int k, int strideB) {
    return (uint32_t)(row * strideB) + ((((k >> 3) ^ (row & 7))) << 4) + ((k & 7) << 1);
}
__device__ __forceinline__ void split_store(char* hi, char* lo, uint32_t off, float v) {
    __nv_bfloat16 h = __float2bfloat16(v);
    *(__nv_bfloat16*)(hi + off) = h;
    *(__nv_bfloat16*)(lo + off) = __float2bfloat16(v - __bfloat162float(h));
}
__device__ __forceinline__ void ldsm4(uint32_t* r, uint32_t addr) {
    asm volatile("ldmatrix.sync.aligned.m8n8.x4.shared.b16 {%0,%1,%2,%3}, [%4];"
        : "=r"(r[0]), "=r"(r[1]), "=r"(r[2]), "=r"(r[3]) : "r"(addr));
}
__device__ __forceinline__ void mma_bf16(float* d, const uint32_t* a, const uint32_t* b) {
    asm volatile("mma.sync.aligned.m16n8k16.row.col.f32.bf16.bf16.f32 "
        "{%0,%1,%2,%3}, {%4,%5,%6,%7}, {%8,%9}, {%0,%1,%2,%3};"
        : "+f"(d[0]), "+f"(d[1]), "+f"(d[2]), "+f"(d[3])
        : "r"(a[0]), "r"(a[1]), "r"(a[2]), "r"(a[3]), "r"(b[0]), "r"(b[1]));
}
__device__ __forceinline__ int seg_of_atom(int g) {
    constexpr int offs[7] = {0,20000,100000,250000,400000,475000,495000};
    int d = 0;
    #pragma unroll
    for (int i = 1; i < 7; i++) if (g >= offs[i]) d = i;
    return d;
}

// ================= weight-image prep =================
// B[n][k] = k<FIN ? Ws[d][k][n] : (d>0 && NBROFF<=k<NBROFF+FIN ? Wn[d-1][k-NBROFF][n] : 0)
template<int FIN, int KPAD, int NBROFF>
__global__ void prep_gcB(const float* __restrict__ Wn, const float* __restrict__ Ws,
                         __nv_bfloat16* __restrict__ outh, __nv_bfloat16* __restrict__ outl)
{
    const int d = blockIdx.x;
    char* bh = (char*)(outh + (size_t)d * 64 * KPAD);
    char* bl = (char*)(outl + (size_t)d * 64 * KPAD);
    for (int idx = threadIdx.x; idx < 64 * KPAD; idx += blockDim.x) {
        int n = idx & 63, k = idx >> 6;
        float v = 0.f;
        if (k < FIN)                                     v = Ws[(size_t)d*FIN*64 + k*64 + n];
        else if (d > 0 && k >= NBROFF && k < NBROFF+FIN) v = Wn[(size_t)(d-1)*FIN*64 + (k-NBROFF)*64 + n];
        split_store(bh, bl, phys(n, k, KPAD*2), v);
    }
}
__global__ void prep_d1B(const float* __restrict__ W)
{
    char* bh = (char*)g_Bdh;
    char* bl = (char*)g_Bdl;
    for (int idx = blockIdx.x * blockDim.x + threadIdx.x; idx < 128 * 64;
         idx += gridDim.x * blockDim.x) {
        int n = idx & 127, k = idx >> 7;
        split_store(bh, bl, phys(n, k, 64*2), W[(size_t)k*128 + n]);
    }
}

// ================= fused graph-conv (mma.sync bf16-split) =================
// Tile: 128 atoms x 64 cols, K = KPAD (self block at 0, nbr block at NBROFF).
// 16 warps: warp w -> rows [ (w>>1)*16 , +16 ), cols [ (w&1)*32, +32 ).
template<int FIN, int KPAD, int NBROFF>
__global__ __launch_bounds__(512) void gc_mma(
    const float* __restrict__ feat, Ptrs P,
    const __nv_bfloat16* __restrict__ Bh, const __nv_bfloat16* __restrict__ Bl,
    const float* __restrict__ bB,
    const float* __restrict__ bng, const float* __restrict__ bnb,
    const float* __restrict__ bnm, const float* __restrict__ bnv,
    float* __restrict__ out)
{
    constexpr int ASTR  = KPAD * 2;           // bytes per A row
    constexpr int A_IMG = 128 * ASTR;
    constexpr int B_IMG = 64 * ASTR;
    constexpr int OFF_BH = 2 * A_IMG;
    constexpr int OFF_C  = 2 * A_IMG + 2 * B_IMG;
    constexpr int NKS = KPAD / 16;

    extern __shared__ char sm[];
    float* s_c = (float*)(sm + OFF_C);        // [bias 64][scale 64][shift 64]
    const uint32_t sbase = smem_u32(sm);

    // tile -> (degree, local tile)
    constexpr int cum[8]    = {0,157,782,1954,3126,3712,3869,3909};
    constexpr int counts[7] = {20000,80000,150000,150000,75000,20000,5000};
    constexpr int offs[7]   = {0,20000,100000,250000,400000,475000,495000};
    int d = 0;
    #pragma unroll
    for (int i = 1; i < 7; i++) if ((int)blockIdx.x >= cum[i]) d = i;
    const int t0    = blockIdx.x - cum[d];
    const int cnt   = counts[d], gbase = offs[d];
    const int tile0 = t0 * 128;
    const int*   adj  = P.adj[d];
    const float* bias = bB + d*64;

    const int tid = threadIdx.x, wid = tid >> 5, lane = tid & 31;

    // zero A images
    for (int i = tid; i < 2*A_IMG/16; i += 512)
        ((uint4*)sm)[i] = make_uint4(0,0,0,0);
    // copy B images (already phys layout)
    {
        const uint4* gh = (const uint4*)(Bh + (size_t)d * 64 * KPAD);
        const uint4* gl = (const uint4*)(Bl + (size_t)d * 64 * KPAD);
        uint4* shh = (uint4*)(sm + OFF_BH);
        uint4* sll = (uint4*)(sm + OFF_BH + B_IMG);
        for (int i = tid; i < B_IMG/16; i += 512) { shh[i] = gh[i]; sll[i] = gl[i]; }
    }
    if (tid < 64) {
        float s = bng[tid] * rsqrtf(bnv[tid] + 1e-3f);
        s_c[tid]       = bias[tid];
        s_c[64 + tid]  = s;
        s_c[128 + tid] = bnb[tid] - bnm[tid]*s;
    }
    __syncthreads();

    // ---- gather: warp per atom (16 warps over 128 atoms) ----
    char* aH = sm;
    char* aL = sm + A_IMG;
    constexpr int NR = (FIN + 31) / 32;
    for (int a = wid; a < 128; a += 16) {
        int la = tile0 + a;
        if (la >= cnt) break;
        float fs[NR], fn[NR];
        #pragma unroll
        for (int r = 0; r < NR; r++) { fs[r] = 0.f; fn[r] = 0.f; }
        const float* row = feat + (size_t)(gbase + la) * FIN;
        #pragma unroll
        for (int r = 0; r < NR; r++) {
            int k = lane + 32*r;
            if ((FIN & 31) == 0 || k < FIN) fs[r] = row[k];
        }
        for (int j = 0; j < d; j++) {
            int nb = adj[(size_t)la * d + j];
            const float* nr = feat + (size_t)nb * FIN;
            #pragma unroll
            for (int r = 0; r < NR; r++) {
                int k = lane + 32*r;
                if ((FIN & 31) == 0 || k < FIN) fn[r] += nr[k];
            }
        }
        #pragma unroll
        for (int r = 0; r < NR; r++) {
            int k = lane + 32*r;
            if ((FIN & 31) == 0 || k < FIN) {
                split_store(aH, aL, phys(a, k, ASTR), fs[r]);
                split_store(aH, aL, phys(a, NBROFF + k, ASTR), fn[r]);
            }
        }
    }
    __syncthreads();

    // ---- MMA mainloop ----
    const int mtile = wid >> 1;          // 0..7
    const int nbase = (wid & 1) * 32;    // 0 or 32
    float acc[4][4] = {};

    // ldmatrix lane addressing
    const int mat = lane >> 3, ir = lane & 7;
    // A: mats (m0-7,klo),(m8-15,klo),(m0-7,khi),(m8-15,khi)
    const int am  = mtile*16 + ir + ((mat & 1) << 3);
    const uint32_t aRow = sbase + am * ASTR;
    const int aKh = mat >> 1, aR7 = am & 7;
    // B: mats (nt0,klo),(nt0,khi),(nt1,klo),(nt1,khi)
    const int bn0 = nbase + ((mat >> 1) << 3) + ir;
    const int bn1 = bn0 + 16;
    const uint32_t bRow0 = sbase + OFF_BH + bn0 * ASTR;
    const uint32_t bRow1 = sbase + OFF_BH + bn1 * ASTR;
    const int bKh = mat & 1, bR70 = bn0 & 7, bR71 = bn1 & 7;

    #pragma unroll
    for (int ks = 0; ks < NKS; ks++) {
        uint32_t ah[4], al[4], bh[8], bl[8];
        uint32_t aA = aRow + ((((ks<<1) | aKh) ^ aR7) << 4);
        ldsm4(ah, aA);
        ldsm4(al, aA + A_IMG);
        uint32_t bA0 = bRow0 + ((((ks<<1) | bKh) ^ bR70) << 4);
        ldsm4(bh + 0, bA0);
        ldsm4(bl + 0, bA0 + B_IMG);
        uint32_t bA1 = bRow1 + ((((ks<<1) | bKh) ^ bR71) << 4);
        ldsm4(bh + 4, bA1);
        ldsm4(bl + 4, bA1 + B_IMG);
        #pragma unroll
        for (int nt = 0; nt < 4; nt++) {
            mma_bf16(acc[nt], ah, &bh[nt*2]);
            mma_bf16(acc[nt], ah, &bl[nt*2]);
            mma_bf16(acc[nt], al, &bh[nt*2]);
        }
    }

    // ---- epilogue: bias -> tanh -> bn -> store ----
    const int r0  = tile0 + mtile*16 + (lane >> 2);
    const int r1  = r0 + 8;
    const int cc  = (lane & 3) * 2;
    #pragma unroll
    for (int nt = 0; nt < 4; nt++) {
        int c = nbase + nt*8 + cc;
        if (r0 < cnt) {
            float2 v;
            v.x = tanhf(acc[nt][0] + s_c[c  ]) * s_c[64+c  ] + s_c[128+c  ];
            v.y = tanhf(acc[nt][1] + s_c[c+1]) * s_c[64+c+1] + s_c[128+c+1];
            *(float2*)&out[(size_t)(gbase + r0)*64 + c] = v;
        }
        if (r1 < cnt) {
            float2 v;
            v.x = tanhf(acc[nt][2] + s_c[c  ]) * s_c[64+c  ] + s_c[128+c  ];
            v.y = tanhf(acc[nt][3] + s_c[c+1]) * s_c[64+c+1] + s_c[128+c+1];
            *(float2*)&out[(size_t)(gbase + r1)*64 + c] = v;
        }
    }
}

// ================= d1 (mma.sync): (Nx64)@(64x128) + tanh + bn3 =================
// Tile 128 rows x 128 cols; warp w: rows (w>>1)*16, cols (w&1)*64 (8 n-tiles).
__global__ __launch_bounds__(512) void d1_mma(
    const float* __restrict__ in, const float* __restrict__ b,
    const float* __restrict__ bng, const float* __restrict__ bnb,
    const float* __restrict__ bnm, const float* __restrict__ bnv,
    float* __restrict__ out)
{
    constexpr int ASTR  = 64 * 2;           // 128 B
    constexpr int A_IMG = 128 * ASTR;       // 16 KB
    constexpr int B_IMG = 128 * ASTR;       // 16 KB (n=128 rows)
    constexpr int OFF_BH = 2 * A_IMG;
    constexpr int OFF_C  = 2 * A_IMG + 2 * B_IMG;

    extern __shared__ char sm[];
    float* s_c = (float*)(sm + OFF_C);      // [b 128][sc 128][sh 128]
    const uint32_t sbase = smem_u32(sm);

    const int tid = threadIdx.x, wid = tid >> 5, lane = tid & 31;
    const int tile0 = blockIdx.x * 128;

    // copy B images
    {
        const uint4* gh = (const uint4*)g_Bdh;
        const uint4* gl = (const uint4*)g_Bdl;
        uint4* shh = (uint4*)(sm + OFF_BH);
        uint4* sll = (uint4*)(sm + OFF_BH + B_IMG);
        for (int i = tid; i < B_IMG/16; i += 512) { shh[i] = gh[i]; sll[i] = gl[i]; }
    }
    if (tid < 128) {
        float s = bng[tid] * rsqrtf(bnv[tid] + 1e-3f);
        s_c[tid]       = b[tid];
        s_c[128 + tid] = s;
        s_c[256 + tid] = bnb[tid] - bnm[tid]*s;
    }
    // fill A (contiguous rows)
    char* aH = sm;
    char* aL = sm + A_IMG;
    for (int idx = tid; idx < 128 * 64; idx += 512) {
        int row = idx >> 6, k = idx & 63;
        int la = tile0 + row;
        float v = (la < NATOMS) ? in[(size_t)la * 64 + k] : 0.f;
        split_store(aH, aL, phys(row, k, ASTR), v);
    }
    __syncthreads();

    const int mtile = wid >> 1;
    const int nbase = (wid & 1) * 64;
    float acc[8][4] = {};

    const int mat = lane >> 3, ir = lane & 7;
    const int am  = mtile*16 + ir + ((mat & 1) << 3);
    const uint32_t aRow = sbase + am * ASTR;
    const int aKh = mat >> 1, aR7 = am & 7;
    const int bnA = nbase + ((mat >> 1) << 3) + ir;   // pair base (+16 per pair)
    const int bKh = mat & 1;

    #pragma unroll
    for (int ks = 0; ks < 4; ks++) {
        uint32_t ah[4], al[4], bh[16], bl[16];
        uint32_t aA = aRow + ((((ks<<1) | aKh) ^ aR7) << 4);
        ldsm4(ah, aA);
        ldsm4(al, aA + A_IMG);
        #pragma unroll
        for (int pr = 0; pr < 4; pr++) {
            int bn = bnA + pr*16;
            uint32_t bA = sbase + OFF_BH + bn * ASTR + ((((ks<<1) | bKh) ^ (bn & 7)) << 4);
            ldsm4(bh + pr*4, bA);
            ldsm4(bl + pr*4, bA + B_IMG);
        }
        #pragma unroll
        for (int nt = 0; nt < 8; nt++) {
            mma_bf16(acc[nt], ah, &bh[nt*2]);
            mma_bf16(acc[nt], ah, &bl[nt*2]);
            mma_bf16(acc[nt], al, &bh[nt*2]);
        }
    }

    const int r0 = tile0 + mtile*16 + (lane >> 2);
    const int r1 = r0 + 8;
    const int cc = (lane & 3) * 2;
    #pragma unroll
    for (int nt = 0; nt < 8; nt++) {
        int c = nbase + nt*8 + cc;
        if (r0 < NATOMS) {
            float2 v;
            v.x = tanhf(acc[nt][0] + s_c[c  ]) * s_c[128+c  ] + s_c[256+c  ];
            v.y = tanhf(acc[nt][1] + s_c[c+1]) * s_c[128+c+1] + s_c[256+c+1];
            *(float2*)&out[(size_t)r0*128 + c] = v;
        }
        if (r1 < NATOMS) {
            float2 v;
            v.x = tanhf(acc[nt][2] + s_c[c  ]) * s_c[128+c  ] + s_c[256+c  ];
            v.y = tanhf(acc[nt][3] + s_c[c+1]) * s_c[128+c+1] + s_c[256+c+1];
            *(float2*)&out[(size_t)r1*128 + c] = v;
        }
    }
}

// ================= graph_pool =================
__global__ __launch_bounds__(256) void pool_all(
    const float* __restrict__ in, Ptrs P, float* __restrict__ out)
{
    int g = (blockIdx.x * 256 + threadIdx.x) >> 4;
    int l = threadIdx.x & 15;
    if (g >= NATOMS) return;
    constexpr int offs[7] = {0,20000,100000,250000,400000,475000,495000};
    int d = seg_of_atom(g);
    int la = g - offs[d];
    float4 m = reinterpret_cast<const float4*>(in + (size_t)g*64)[l];
    const int* adj = P.adj[d];
    for (int j = 0; j < d; j++) {
        int nb = adj[(size_t)la * d + j];
        float4 v = reinterpret_cast<const float4*>(in + (size_t)nb*64)[l];
        m.x = fmaxf(m.x, v.x); m.y = fmaxf(m.y, v.y);
        m.z = fmaxf(m.z, v.z); m.w = fmaxf(m.w, v.w);
    }
    reinterpret_cast<float4*>(out + (size_t)g*64)[l] = m;
}

// ================= counting sort =================
__global__ void zero_cnt_kernel() {
    int i = blockIdx.x * blockDim.x + threadIdx.x;
    if (i < NBATCH) g_cnt[i] = 0;
}
__global__ void hist_kernel(const int* __restrict__ mem) {
    int i = blockIdx.x * blockDim.x + threadIdx.x;
    if (i < NATOMS) atomicAdd(&g_cnt[mem[i]], 1);
}
__global__ void scan_kernel() {
    __shared__ int s[NBATCH];
    int t = threadIdx.x;
    s[t] = g_cnt[t];
    __syncthreads();
    for (int ofs = 1; ofs < NBATCH; ofs <<= 1) {
        int v = (t >= ofs) ? s[t - ofs] : 0;
        __syncthreads();
        s[t] += v;
        __syncthreads();
    }
    g_off[t+1] = s[t];
    if (t == 0) g_off[0] = 0;
    g_cur[t] = s[t] - g_cnt[t];
}
__global__ void scatter_kernel(const int* __restrict__ mem) {
    int i = blockIdx.x * blockDim.x + threadIdx.x;
    if (i < NATOMS) {
        int p = atomicAdd(&g_cur[mem[i]], 1);
        g_sorted[p] = i;
    }
}

// ================= segment reduce + final MLP =================
__global__ __launch_bounds__(128) void reduce_kernel(
    const float* __restrict__ d2W, const float* __restrict__ d2b,
    const float* __restrict__ d3W, const float* __restrict__ d3b,
    float* __restrict__ outp)
{
    __shared__ float gs[256];
    __shared__ int   sidx[512];
    __shared__ float ssig[64];
    const int b = blockIdx.x, t = threadIdx.x;
    const int start = g_off[b], end = g_off[b+1];

    float sum = 0.f, mx = -INFINITY;
    for (int base = start; base < end; base += 512) {
        int n = min(512, end - base);
        for (int i = t; i < n; i += 128) sidx[i] = g_sorted[base + i];
        __syncthreads();
        int i = 0;
        for (; i + 4 <= n; i += 4) {
            float v0 = g_p[(size_t)sidx[i+0]*128 + t];
            float v1 = g_p[(size_t)sidx[i+1]*128 + t];
            float v2 = g_p[(size_t)sidx[i+2]*128 + t];
            float v3 = g_p[(size_t)sidx[i+3]*128 + t];
            sum += (v0 + v1) + (v2 + v3);
            mx = fmaxf(mx, fmaxf(fmaxf(v0, v1), fmaxf(v2, v3)));
        }
        for (; i < n; i++) {
            float v = g_p[(size_t)sidx[i]*128 + t];
            sum += v; mx = fmaxf(mx, v);
        }
        __syncthreads();
    }
    gs[t]       = tanhf(sum);
    gs[128 + t] = tanhf(mx);
    __syncthreads();

    if (t < 64) {
        float a = d2b[t];
        #pragma unroll 4
        for (int k = 0; k < 256; k++) a += gs[k] * __ldg(&d2W[k*64 + t]);
        ssig[t] = 1.f / (1.f + expf(-a));
    }
    __syncthreads();
    if (t < 32) {
        float v = ssig[t]*__ldg(&d3W[t]) + ssig[t+32]*__ldg(&d3W[t+32]);
        #pragma unroll
        for (int o = 16; o; o >>= 1) v += __shfl_down_sync(0xffffffffu, v, o);
        if (t == 0) outp[b] = v + d3b[0];
    }
}

// ================= launch =================
extern "C" void kernel_launch(void* const* d_in, const int* in_sizes, int n_in,
                              void* d_out, int out_size)
{
    const float* feat       = (const float*)d_in[0];
    const int*   membership = (const int*)  d_in[1];
    Ptrs P;
    P.adj[0] = nullptr;
    for (int d = 1; d <= 6; d++) P.adj[d] = (const int*)d_in[1 + d];
    const float* gc1_Wn = (const float*)d_in[8];
    const float* gc1_Ws = (const float*)d_in[9];
    const float* gc1_b  = (const float*)d_in[10];
    const float* gc2_Wn = (const float*)d_in[11];
    const float* gc2_Ws = (const float*)d_in[12];
    const float* gc2_b  = (const float*)d_in[13];
    const float* bn1g = (const float*)d_in[14];
    const float* bn1b = (const float*)d_in[15];
    const float* bn1m = (const float*)d_in[16];
    const float* bn1v = (const float*)d_in[17];
    const float* bn3g = (const float*)d_in[18];
    const float* bn3b = (const float*)d_in[19];
    const float* bn3m = (const float*)d_in[20];
    const float* bn3v = (const float*)d_in[21];
    const float* d1W = (const float*)d_in[22];
    const float* d1b = (const float*)d_in[23];
    const float* d2W = (const float*)d_in[24];
    const float* d2b = (const float*)d_in[25];
    const float* d3W = (const float*)d_in[26];
    const float* d3b = (const float*)d_in[27];

    void* pp;
    cudaGetSymbolAddress(&pp, g_h1); float* h1 = (float*)pp;
    cudaGetSymbolAddress(&pp, g_h2); float* h2 = (float*)pp;
    cudaGetSymbolAddress(&pp, g_p);  float* pf = (float*)pp;
    __nv_bfloat16 *b1h, *b1l, *b2h, *b2l;
    cudaGetSymbolAddress(&pp, g_B1h); b1h = (__nv_bfloat16*)pp;
    cudaGetSymbolAddress(&pp, g_B1l); b1l = (__nv_bfloat16*)pp;
    cudaGetSymbolAddress(&pp, g_B2h); b2h = (__nv_bfloat16*)pp;
    cudaGetSymbolAddress(&pp, g_B2l); b2l = (__nv_bfloat16*)pp;

    // smem: 2*A_IMG + 2*B_IMG + 192(or 384)*4
    const int SM_GC1 = 2*(128*192*2) + 2*(64*192*2) + 192*4;   // 148,224
    const int SM_GC2 = 2*(128*128*2) + 2*(64*128*2) + 192*4;   //  99,072
    const int SM_D1  = 2*(128*64*2)  + 2*(128*64*2) + 384*4;   //  67,072
    cudaFuncSetAttribute((const void*)gc_mma<75,192,80>, cudaFuncAttributeMaxDynamicSharedMemorySize, SM_GC1);
    cudaFuncSetAttribute((const void*)gc_mma<64,128,64>, cudaFuncAttributeMaxDynamicSharedMemorySize, SM_GC2);
    cudaFuncSetAttribute((const void*)d1_mma,            cudaFuncAttributeMaxDynamicSharedMemorySize, SM_D1);

    // weight images
    prep_gcB<75,192,80><<<7,256>>>(gc1_Wn, gc1_Ws, b1h, b1l);
    prep_gcB<64,128,64><<<7,256>>>(gc2_Wn, gc2_Ws, b2h, b2l);
    prep_d1B<<<32,256>>>(d1W);

    const int GC_GRID   = 3909;  // 128-atom tiles over 7 segments
    const int POOL_GRID = (NATOMS*16 + 255) / 256;

    gc_mma<75,192,80><<<GC_GRID, 512, SM_GC1>>>(feat, P, b1h, b1l, gc1_b,
                                                bn1g, bn1b, bn1m, bn1v, h1);
    pool_all<<<POOL_GRID, 256>>>(h1, P, h2);
    gc_mma<64,128,64><<<GC_GRID, 512, SM_GC2>>>(h2, P, b2h, b2l, gc2_b,
                                                bn1g, bn1b, bn1m, bn1v, h1);
    pool_all<<<POOL_GRID, 256>>>(h1, P, h2);
    d1_mma<<<(NATOMS + 127)/128, 512, SM_D1>>>(h2, d1b, bn3g, bn3b, bn3m, bn3v, pf);

    zero_cnt_kernel<<<(NBATCH + 255)/256, 256>>>();
    hist_kernel<<<(NATOMS + 255)/256, 256>>>(membership);
    scan_kernel<<<1, 1024>>>();
    scatter_kernel<<<(NATOMS + 255)/256, 256>>>(membership);
    reduce_kernel<<<NBATCH, 128>>>(d2W, d2b, d3W, d3b, (float*)d_out);
}

// round 6
// speedup vs baseline: 2.2010x; 1.2288x over previous
#include <cuda_runtime.h>
#include <cuda_bf16.h>
#include <math.h>
#include <cstdint>

#define NATOMS 500000
#define NBATCH 1024

// ================= scratch =================
__device__ float g_h1[(size_t)NATOMS*64];
__device__ float g_h2[(size_t)NATOMS*64];
__device__ float g_p [(size_t)NATOMS*128];
__device__ int   g_cnt[NBATCH];
__device__ int   g_off[NBATCH+1];
__device__ int   g_cur[NBATCH];
__device__ int   g_sorted[NATOMS];
// B operands in mma-fragment order: [d][ks][nt][lane] -> uint4{bh0,bh1,bl0,bl1}
__device__ uint4 g_F1[7*12*8*32];   // gc1: NKS=12, 8 ntiles
__device__ uint4 g_F2[7*8*8*32];    // gc2: NKS=8,  8 ntiles
__device__ uint4 g_Fd[4*16*32];     // d1 : NKS=4, 16 ntiles

struct Ptrs { const int* adj[7]; };

// ================= helpers =================
__device__ __forceinline__ uint32_t smem_u32(const void* p) {
    uint32_t a;
    asm("{ .reg .u64 t; cvta.to.shared.u64 t, %1; cvt.u32.u64 %0, t; }" : "=r"(a) : "l"(p));
    return a;
}
// [row][k] bf16 image, 16B-chunk swizzle: chunk ^= (row&7); needs chunks/row mult of 8
__device__ __forceinline__ uint32_t phys(int row, int k, int strideB) {
    return (uint32_t)(row * strideB) + ((((k >> 3) ^ (row & 7))) << 4) + ((k & 7) << 1);
}
__device__ __forceinline__ void split_store(char* hi, char* lo, uint32_t off, float v) {
    __nv_bfloat16 h = __float2bfloat16(v);
    *(__nv_bfloat16*)(hi + off) = h;
    *(__nv_bfloat16*)(lo + off) = __float2bfloat16(v - __bfloat162float(h));
}
__device__ __forceinline__ void split2(float a, float b, uint32_t& hi, uint32_t& lo) {
    __nv_bfloat16 ha = __float2bfloat16(a), hb = __float2bfloat16(b);
    __nv_bfloat16 la = __float2bfloat16(a - __bfloat162float(ha));
    __nv_bfloat16 lb = __float2bfloat16(b - __bfloat162float(hb));
    hi = ((uint32_t)__bfloat16_as_ushort(hb) << 16) | __bfloat16_as_ushort(ha);
    lo = ((uint32_t)__bfloat16_as_ushort(lb) << 16) | __bfloat16_as_ushort(la);
}
__device__ __forceinline__ void ldsm4(uint32_t* r, uint32_t addr) {
    asm volatile("ldmatrix.sync.aligned.m8n8.x4.shared.b16 {%0,%1,%2,%3}, [%4];"
        : "=r"(r[0]), "=r"(r[1]), "=r"(r[2]), "=r"(r[3]) : "r"(addr));
}
__device__ __forceinline__ void mma_bf16(float* d, const uint32_t* a, uint32_t b0, uint32_t b1) {
    asm volatile("mma.sync.aligned.m16n8k16.row.col.f32.bf16.bf16.f32 "
        "{%0,%1,%2,%3}, {%4,%5,%6,%7}, {%8,%9}, {%0,%1,%2,%3};"
        : "+f"(d[0]), "+f"(d[1]), "+f"(d[2]), "+f"(d[3])
        : "r"(a[0]), "r"(a[1]), "r"(a[2]), "r"(a[3]), "r"(b0), "r"(b1));
}
__device__ __forceinline__ int seg_of_atom(int g) {
    constexpr int offs[7] = {0,20000,100000,250000,400000,475000,495000};
    int d = 0;
    #pragma unroll
    for (int i = 1; i < 7; i++) if (g >= offs[i]) d = i;
    return d;
}

// ================= fragment prep =================
// logical B[n][k]: k<FIN -> Ws[d][k][n]; d>0 && NBROFF<=k<NBROFF+FIN -> Wn[d-1][k-NBROFF][n]; else 0
template<int FIN, int NBROFF, int NKS>
__global__ void prep_frags_gc(const float* __restrict__ Wn, const float* __restrict__ Ws,
                              uint4* __restrict__ out)
{
    const int d = blockIdx.x;
    for (int idx = threadIdx.x; idx < NKS*8*32; idx += blockDim.x) {
        int lane = idx & 31, nt = (idx >> 5) & 7, ks = idx >> 8;
        int n  = nt*8 + (lane >> 2);
        int k0 = ks*16 + (lane & 3)*2;
        float v[4];
        #pragma unroll
        for (int i = 0; i < 4; i++) {
            int k = k0 + (i >> 1)*8 + (i & 1);
            float x = 0.f;
            if (k < FIN) x = Ws[(size_t)d*FIN*64 + (size_t)k*64 + n];
            else if (d > 0 && k >= NBROFF && k < NBROFF+FIN)
                x = Wn[(size_t)(d-1)*FIN*64 + (size_t)(k-NBROFF)*64 + n];
            v[i] = x;
        }
        uint4 f;
        split2(v[0], v[1], f.x, f.z);
        split2(v[2], v[3], f.y, f.w);
        out[((d*NKS + ks)*8 + nt)*32 + lane] = f;
    }
}
__global__ void prep_frags_d1(const float* __restrict__ W)
{
    for (int idx = threadIdx.x; idx < 4*16*32; idx += blockDim.x) {
        int lane = idx & 31, nt = (idx >> 5) & 15, ks = idx >> 9;
        int n  = nt*8 + (lane >> 2);
        int k0 = ks*16 + (lane & 3)*2;
        float v[4];
        #pragma unroll
        for (int i = 0; i < 4; i++) {
            int k = k0 + (i >> 1)*8 + (i & 1);
            v[i] = W[(size_t)k*128 + n];
        }
        uint4 f;
        split2(v[0], v[1], f.x, f.z);
        split2(v[2], v[3], f.y, f.w);
        g_Fd[(ks*16 + nt)*32 + lane] = f;
    }
}

// ================= fused graph-conv (mma.sync, B frags from global) =================
// Tile: 128 atoms x 64 cols, K=KPAD (self @0, nbr @NBROFF). 16 warps.
template<int FIN, int KPAD, int NBROFF, int NKS>
__global__ __launch_bounds__(512, 2) void gc_mma(
    const float* __restrict__ feat, Ptrs P,
    const uint4* __restrict__ frags,
    const float* __restrict__ bB,
    const float* __restrict__ bng, const float* __restrict__ bnb,
    const float* __restrict__ bnm, const float* __restrict__ bnv,
    float* __restrict__ out)
{
    constexpr int ASTR  = KPAD * 2;
    constexpr int A_IMG = 128 * ASTR;
    constexpr int OFF_C = 2 * A_IMG;

    extern __shared__ char sm[];
    float* s_c = (float*)(sm + OFF_C);   // [bias 64][scale 64][shift 64]
    const uint32_t sbase = smem_u32(sm);

    constexpr int cum[8]    = {0,157,782,1954,3126,3712,3869,3909};
    constexpr int counts[7] = {20000,80000,150000,150000,75000,20000,5000};
    constexpr int offs[7]   = {0,20000,100000,250000,400000,475000,495000};
    int d = 0;
    #pragma unroll
    for (int i = 1; i < 7; i++) if ((int)blockIdx.x >= cum[i]) d = i;
    const int t0    = blockIdx.x - cum[d];
    const int cnt   = counts[d], gbase = offs[d];
    const int tile0 = t0 * 128;
    const int* adj  = P.adj[d];
    const float* bias = bB + d*64;

    const int tid = threadIdx.x, wid = tid >> 5, lane = tid & 31;

    // zero A images
    for (int i = tid; i < 2*A_IMG/16; i += 512)
        ((uint4*)sm)[i] = make_uint4(0,0,0,0);
    if (tid < 64) {
        float s = bng[tid] * rsqrtf(bnv[tid] + 1e-3f);
        s_c[tid]       = bias[tid];
        s_c[64 + tid]  = s;
        s_c[128 + tid] = bnb[tid] - bnm[tid]*s;
    }
    __syncthreads();

    // ---- gather: warp per atom (predicated 6-way neighbor unroll) ----
    char* aH = sm;
    char* aL = sm + A_IMG;
    constexpr int NR = (FIN + 31) / 32;
    for (int a = wid; a < 128; a += 16) {
        int la = tile0 + a;
        if (la >= cnt) break;
        const float* selfr = feat + (size_t)(gbase + la) * FIN;
        const float* nrp[6];
        #pragma unroll
        for (int j = 0; j < 6; j++) {
            int nb = (j < d) ? adj[(size_t)la * d + j] : (gbase + la);
            nrp[j] = feat + (size_t)nb * FIN;
        }
        float fs[NR], tv[6][NR];
        #pragma unroll
        for (int r = 0; r < NR; r++) {
            int k = lane + 32*r;
            bool ok = ((FIN & 31) == 0) || (k < FIN);
            fs[r] = ok ? selfr[k] : 0.f;
            #pragma unroll
            for (int j = 0; j < 6; j++) tv[j][r] = ok ? nrp[j][k] : 0.f;
        }
        float fn[NR];
        #pragma unroll
        for (int r = 0; r < NR; r++) {
            fn[r] = 0.f;
            #pragma unroll
            for (int j = 0; j < 6; j++) if (j < d) fn[r] += tv[j][r];
        }
        #pragma unroll
        for (int r = 0; r < NR; r++) {
            int k = lane + 32*r;
            if ((FIN & 31) == 0 || k < FIN) {
                split_store(aH, aL, phys(a, k, ASTR), fs[r]);
                split_store(aH, aL, phys(a, NBROFF + k, ASTR), fn[r]);
            }
        }
    }
    __syncthreads();

    // ---- MMA mainloop ----
    const int mtile = wid >> 1;
    const int nb8   = (wid & 1) * 4;      // ntile base (n8 units)
    float acc[4][4] = {};

    const int mat = lane >> 3, ir = lane & 7;
    const int am  = mtile*16 + ir + ((mat & 1) << 3);
    const uint32_t aRow = sbase + am * ASTR;
    const int aKh = mat >> 1, aR7 = am & 7;
    const uint4* fw = frags + (size_t)(d * NKS) * 8 * 32;

    #pragma unroll
    for (int ks = 0; ks < NKS; ks++) {
        uint32_t ah[4], al[4];
        uint32_t aA = aRow + ((((ks<<1) | aKh) ^ aR7) << 4);
        ldsm4(ah, aA);
        ldsm4(al, aA + A_IMG);
        uint4 f0 = fw[(ks*8 + nb8 + 0)*32 + lane];
        uint4 f1 = fw[(ks*8 + nb8 + 1)*32 + lane];
        uint4 f2 = fw[(ks*8 + nb8 + 2)*32 + lane];
        uint4 f3 = fw[(ks*8 + nb8 + 3)*32 + lane];
        mma_bf16(acc[0], ah, f0.x, f0.y); mma_bf16(acc[0], ah, f0.z, f0.w); mma_bf16(acc[0], al, f0.x, f0.y);
        mma_bf16(acc[1], ah, f1.x, f1.y); mma_bf16(acc[1], ah, f1.z, f1.w); mma_bf16(acc[1], al, f1.x, f1.y);
        mma_bf16(acc[2], ah, f2.x, f2.y); mma_bf16(acc[2], ah, f2.z, f2.w); mma_bf16(acc[2], al, f2.x, f2.y);
        mma_bf16(acc[3], ah, f3.x, f3.y); mma_bf16(acc[3], ah, f3.z, f3.w); mma_bf16(acc[3], al, f3.x, f3.y);
    }

    // ---- epilogue ----
    const int r0 = tile0 + mtile*16 + (lane >> 2);
    const int r1 = r0 + 8;
    const int cc = (lane & 3) * 2;
    const int nbase = nb8 * 8;
    #pragma unroll
    for (int nt = 0; nt < 4; nt++) {
        int c = nbase + nt*8 + cc;
        if (r0 < cnt) {
            float2 v;
            v.x = tanhf(acc[nt][0] + s_c[c  ]) * s_c[64+c  ] + s_c[128+c  ];
            v.y = tanhf(acc[nt][1] + s_c[c+1]) * s_c[64+c+1] + s_c[128+c+1];
            *(float2*)&out[(size_t)(gbase + r0)*64 + c] = v;
        }
        if (r1 < cnt) {
            float2 v;
            v.x = tanhf(acc[nt][2] + s_c[c  ]) * s_c[64+c  ] + s_c[128+c  ];
            v.y = tanhf(acc[nt][3] + s_c[c+1]) * s_c[64+c+1] + s_c[128+c+1];
            *(float2*)&out[(size_t)(gbase + r1)*64 + c] = v;
        }
    }
}

// ================= d1 (mma.sync, B frags from global) =================
__global__ __launch_bounds__(512, 2) void d1_mma(
    const float* __restrict__ in, const float* __restrict__ b,
    const float* __restrict__ bng, const float* __restrict__ bnb,
    const float* __restrict__ bnm, const float* __restrict__ bnv,
    float* __restrict__ out)
{
    constexpr int ASTR  = 128;           // 64 bf16
    constexpr int A_IMG = 128 * ASTR;    // 16 KB
    constexpr int OFF_C = 2 * A_IMG;

    extern __shared__ char sm[];
    float* s_c = (float*)(sm + OFF_C);   // [b 128][sc 128][sh 128]
    const uint32_t sbase = smem_u32(sm);

    const int tid = threadIdx.x, wid = tid >> 5, lane = tid & 31;
    const int tile0 = blockIdx.x * 128;

    if (tid < 128) {
        float s = bng[tid] * rsqrtf(bnv[tid] + 1e-3f);
        s_c[tid]       = b[tid];
        s_c[128 + tid] = s;
        s_c[256 + tid] = bnb[tid] - bnm[tid]*s;
    }
    char* aH = sm;
    char* aL = sm + A_IMG;
    for (int idx = tid; idx < 128 * 64; idx += 512) {
        int row = idx >> 6, k = idx & 63;
        int la = tile0 + row;
        float v = (la < NATOMS) ? in[(size_t)la * 64 + k] : 0.f;
        split_store(aH, aL, phys(row, k, ASTR), v);
    }
    __syncthreads();

    const int mtile = wid >> 1;
    const int nb8   = (wid & 1) * 8;
    float acc[8][4] = {};

    const int mat = lane >> 3, ir = lane & 7;
    const int am  = mtile*16 + ir + ((mat & 1) << 3);
    const uint32_t aRow = sbase + am * ASTR;
    const int aKh = mat >> 1, aR7 = am & 7;

    #pragma unroll
    for (int ks = 0; ks < 4; ks++) {
        uint32_t ah[4], al[4];
        uint32_t aA = aRow + ((((ks<<1) | aKh) ^ aR7) << 4);
        ldsm4(ah, aA);
        ldsm4(al, aA + A_IMG);
        #pragma unroll
        for (int nt = 0; nt < 8; nt++) {
            uint4 f = g_Fd[(ks*16 + nb8 + nt)*32 + lane];
            mma_bf16(acc[nt], ah, f.x, f.y);
            mma_bf16(acc[nt], ah, f.z, f.w);
            mma_bf16(acc[nt], al, f.x, f.y);
        }
    }

    const int r0 = tile0 + mtile*16 + (lane >> 2);
    const int r1 = r0 + 8;
    const int cc = (lane & 3) * 2;
    const int nbase = nb8 * 8;
    #pragma unroll
    for (int nt = 0; nt < 8; nt++) {
        int c = nbase + nt*8 + cc;
        if (r0 < NATOMS) {
            float2 v;
            v.x = tanhf(acc[nt][0] + s_c[c  ]) * s_c[128+c  ] + s_c[256+c  ];
            v.y = tanhf(acc[nt][1] + s_c[c+1]) * s_c[128+c+1] + s_c[256+c+1];
            *(float2*)&out[(size_t)r0*128 + c] = v;
        }
        if (r1 < NATOMS) {
            float2 v;
            v.x = tanhf(acc[nt][2] + s_c[c  ]) * s_c[128+c  ] + s_c[256+c  ];
            v.y = tanhf(acc[nt][3] + s_c[c+1]) * s_c[128+c+1] + s_c[256+c+1];
            *(float2*)&out[(size_t)r1*128 + c] = v;
        }
    }
}

// ================= graph_pool (predicated 6-way unroll) =================
__global__ __launch_bounds__(256) void pool_all(
    const float* __restrict__ in, Ptrs P, float* __restrict__ out)
{
    int g = (blockIdx.x * 256 + threadIdx.x) >> 4;
    int l = threadIdx.x & 15;
    if (g >= NATOMS) return;
    constexpr int offs[7] = {0,20000,100000,250000,400000,475000,495000};
    int d = seg_of_atom(g);
    int la = g - offs[d];
    const int* adj = P.adj[d];
    int nb[6];
    #pragma unroll
    for (int j = 0; j < 6; j++)
        nb[j] = (j < d) ? adj[(size_t)la * d + j] : g;
    float4 m = reinterpret_cast<const float4*>(in + (size_t)g*64)[l];
    float4 v[6];
    #pragma unroll
    for (int j = 0; j < 6; j++)
        v[j] = reinterpret_cast<const float4*>(in + (size_t)nb[j]*64)[l];
    #pragma unroll
    for (int j = 0; j < 6; j++) {
        m.x = fmaxf(m.x, v[j].x); m.y = fmaxf(m.y, v[j].y);
        m.z = fmaxf(m.z, v[j].z); m.w = fmaxf(m.w, v[j].w);
    }
    reinterpret_cast<float4*>(out + (size_t)g*64)[l] = m;
}

// ================= counting sort =================
__global__ void zero_cnt_kernel() {
    int i = blockIdx.x * blockDim.x + threadIdx.x;
    if (i < NBATCH) g_cnt[i] = 0;
}
__global__ void hist_kernel(const int* __restrict__ mem) {
    int i = blockIdx.x * blockDim.x + threadIdx.x;
    if (i < NATOMS) atomicAdd(&g_cnt[mem[i]], 1);
}
__global__ void scan_kernel() {
    __shared__ int s[NBATCH];
    int t = threadIdx.x;
    s[t] = g_cnt[t];
    __syncthreads();
    for (int ofs = 1; ofs < NBATCH; ofs <<= 1) {
        int v = (t >= ofs) ? s[t - ofs] : 0;
        __syncthreads();
        s[t] += v;
        __syncthreads();
    }
    g_off[t+1] = s[t];
    if (t == 0) g_off[0] = 0;
    g_cur[t] = s[t] - g_cnt[t];
}
__global__ void scatter_kernel(const int* __restrict__ mem) {
    int i = blockIdx.x * blockDim.x + threadIdx.x;
    if (i < NATOMS) {
        int p = atomicAdd(&g_cur[mem[i]], 1);
        g_sorted[p] = i;
    }
}

// ================= segment reduce + final MLP =================
__global__ __launch_bounds__(128) void reduce_kernel(
    const float* __restrict__ d2W, const float* __restrict__ d2b,
    const float* __restrict__ d3W, const float* __restrict__ d3b,
    float* __restrict__ outp)
{
    __shared__ float gs[256];
    __shared__ int   sidx[512];
    __shared__ float ssig[64];
    const int b = blockIdx.x, t = threadIdx.x;
    const int start = g_off[b], end = g_off[b+1];

    float sum = 0.f, mx = -INFINITY;
    for (int base = start; base < end; base += 512) {
        int n = min(512, end - base);
        for (int i = t; i < n; i += 128) sidx[i] = g_sorted[base + i];
        __syncthreads();
        int i = 0;
        for (; i + 4 <= n; i += 4) {
            float v0 = g_p[(size_t)sidx[i+0]*128 + t];
            float v1 = g_p[(size_t)sidx[i+1]*128 + t];
            float v2 = g_p[(size_t)sidx[i+2]*128 + t];
            float v3 = g_p[(size_t)sidx[i+3]*128 + t];
            sum += (v0 + v1) + (v2 + v3);
            mx = fmaxf(mx, fmaxf(fmaxf(v0, v1), fmaxf(v2, v3)));
        }
        for (; i < n; i++) {
            float v = g_p[(size_t)sidx[i]*128 + t];
            sum += v; mx = fmaxf(mx, v);
        }
        __syncthreads();
    }
    gs[t]       = tanhf(sum);
    gs[128 + t] = tanhf(mx);
    __syncthreads();

    if (t < 64) {
        float a = d2b[t];
        #pragma unroll 4
        for (int k = 0; k < 256; k++) a += gs[k] * __ldg(&d2W[k*64 + t]);
        ssig[t] = 1.f / (1.f + expf(-a));
    }
    __syncthreads();
    if (t < 32) {
        float v = ssig[t]*__ldg(&d3W[t]) + ssig[t+32]*__ldg(&d3W[t+32]);
        #pragma unroll
        for (int o = 16; o; o >>= 1) v += __shfl_down_sync(0xffffffffu, v, o);
        if (t == 0) outp[b] = v + d3b[0];
    }
}

// ================= launch =================
extern "C" void kernel_launch(void* const* d_in, const int* in_sizes, int n_in,
                              void* d_out, int out_size)
{
    const float* feat       = (const float*)d_in[0];
    const int*   membership = (const int*)  d_in[1];
    Ptrs P;
    P.adj[0] = nullptr;
    for (int d = 1; d <= 6; d++) P.adj[d] = (const int*)d_in[1 + d];
    const float* gc1_Wn = (const float*)d_in[8];
    const float* gc1_Ws = (const float*)d_in[9];
    const float* gc1_b  = (const float*)d_in[10];
    const float* gc2_Wn = (const float*)d_in[11];
    const float* gc2_Ws = (const float*)d_in[12];
    const float* gc2_b  = (const float*)d_in[13];
    const float* bn1g = (const float*)d_in[14];
    const float* bn1b = (const float*)d_in[15];
    const float* bn1m = (const float*)d_in[16];
    const float* bn1v = (const float*)d_in[17];
    const float* bn3g = (const float*)d_in[18];
    const float* bn3b = (const float*)d_in[19];
    const float* bn3m = (const float*)d_in[20];
    const float* bn3v = (const float*)d_in[21];
    const float* d1W = (const float*)d_in[22];
    const float* d1b = (const float*)d_in[23];
    const float* d2W = (const float*)d_in[24];
    const float* d2b = (const float*)d_in[25];
    const float* d3W = (const float*)d_in[26];
    const float* d3b = (const float*)d_in[27];

    void* pp;
    cudaGetSymbolAddress(&pp, g_h1); float* h1 = (float*)pp;
    cudaGetSymbolAddress(&pp, g_h2); float* h2 = (float*)pp;
    cudaGetSymbolAddress(&pp, g_p);  float* pf = (float*)pp;
    uint4 *f1, *f2;
    cudaGetSymbolAddress(&pp, g_F1); f1 = (uint4*)pp;
    cudaGetSymbolAddress(&pp, g_F2); f2 = (uint4*)pp;

    const int SM_GC1 = 2*(128*192*2) + 192*4;   // 99,072
    const int SM_GC2 = 2*(128*128*2) + 192*4;   // 66,304
    const int SM_D1  = 2*(128*64*2)  + 384*4;   // 34,304
    cudaFuncSetAttribute((const void*)gc_mma<75,192,80,12>, cudaFuncAttributeMaxDynamicSharedMemorySize, SM_GC1);
    cudaFuncSetAttribute((const void*)gc_mma<64,128,64,8>,  cudaFuncAttributeMaxDynamicSharedMemorySize, SM_GC2);
    cudaFuncSetAttribute((const void*)d1_mma,               cudaFuncAttributeMaxDynamicSharedMemorySize, SM_D1);

    // B fragments
    prep_frags_gc<75,80,12><<<7,256>>>(gc1_Wn, gc1_Ws, f1);
    prep_frags_gc<64,64,8><<<7,256>>>(gc2_Wn, gc2_Ws, f2);
    prep_frags_d1<<<1,512>>>(d1W);

    const int GC_GRID   = 3909;
    const int POOL_GRID = (NATOMS*16 + 255) / 256;

    gc_mma<75,192,80,12><<<GC_GRID, 512, SM_GC1>>>(feat, P, f1, gc1_b,
                                                   bn1g, bn1b, bn1m, bn1v, h1);
    pool_all<<<POOL_GRID, 256>>>(h1, P, h2);
    gc_mma<64,128,64,8><<<GC_GRID, 512, SM_GC2>>>(h2, P, f2, gc2_b,
                                                  bn1g, bn1b, bn1m, bn1v, h1);
    pool_all<<<POOL_GRID, 256>>>(h1, P, h2);
    d1_mma<<<(NATOMS + 127)/128, 512, SM_D1>>>(h2, d1b, bn3g, bn3b, bn3m, bn3v, pf);

    zero_cnt_kernel<<<(NBATCH + 255)/256, 256>>>();
    hist_kernel<<<(NATOMS + 255)/256, 256>>>(membership);
    scan_kernel<<<1, 1024>>>();
    scatter_kernel<<<(NATOMS + 255)/256, 256>>>(membership);
    reduce_kernel<<<NBATCH, 128>>>(d2W, d2b, d3W, d3b, (float*)d_out);
}